// round 8
// baseline (speedup 1.0000x reference)
#include <cuda_runtime.h>
#include <math.h>

#define D 512
#define K 5
#define TPB 128          // one row per block-iteration; thread t owns d = 4t..4t+3
#define NBLOCKS 2048     // grid-stride over rows

__global__ __launch_bounds__(TPB) void lfr_blockrow_kernel(
    const float* __restrict__ x,
    const float* __restrict__ alpha,
    const float* __restrict__ classif_w,
    const float* __restrict__ centroids,
    float* __restrict__ out_map,   // (N, K)
    float* __restrict__ out_rec,   // (N, D)
    float* __restrict__ out_pred,  // (N,)
    int n)
{
    const int t    = threadIdx.x;
    const int lane = t & 31;
    const int warp = t >> 5;
    const int d0   = t * 4;

    // Per-thread slice caches: 20 + 4 regs
    float4 a4 = *(const float4*)(alpha + d0);
    float4 c4[K];
#pragma unroll
    for (int k = 0; k < K; k++)
        c4[k] = *(const float4*)(centroids + k * D + d0);

    float sw[K];
#pragma unroll
    for (int k = 0; k < K; k++)
        sw[k] = 1.0f / (1.0f + __expf(-classif_w[k]));  // broadcast loads

    __shared__ float s_part[2][4][K];  // [parity][warp][k]

    // b[k] = sum_d alpha_d * c_kd^2  (one block-reduce at start)
    float b[K];
    {
        float p[K];
#pragma unroll
        for (int k = 0; k < K; k++) {
            p[k] = a4.x * c4[k].x * c4[k].x + a4.y * c4[k].y * c4[k].y +
                   a4.z * c4[k].z * c4[k].z + a4.w * c4[k].w * c4[k].w;
#pragma unroll
            for (int o = 16; o; o >>= 1) p[k] += __shfl_xor_sync(0xffffffffu, p[k], o);
        }
        if (lane == 0) {
#pragma unroll
            for (int k = 0; k < K; k++) s_part[0][warp][k] = p[k];
        }
        __syncthreads();
#pragma unroll
        for (int k = 0; k < K; k++)
            b[k] = s_part[0][0][k] + s_part[0][1][k] + s_part[0][2][k] + s_part[0][3][k];
        __syncthreads();  // buffer 0 reused below
    }

    int row = blockIdx.x;
    if (row >= n) return;

    float4 xv = ((const float4*)(x + (size_t)row * D))[t];
    int par = 0;

    while (row < n) {
        const int next = row + gridDim.x;
        float4 xn;
        if (next < n) xn = ((const float4*)(x + (size_t)next * D))[t];

        // Per-thread partial dots: dot_k = sum_d alpha*x*c
        const float tx = xv.x * a4.x, ty = xv.y * a4.y;
        const float tz = xv.z * a4.z, tw = xv.w * a4.w;
        float p[K];
#pragma unroll
        for (int k = 0; k < K; k++) {
            p[k] = tx * c4[k].x + ty * c4[k].y + tz * c4[k].z + tw * c4[k].w;
#pragma unroll
            for (int o = 16; o; o >>= 1) p[k] += __shfl_xor_sync(0xffffffffu, p[k], o);
        }
        if (lane == 0) {
#pragma unroll
            for (int k = 0; k < K; k++) s_part[par][warp][k] = p[k];
        }
        __syncthreads();
        // Single barrier per row is race-free: a thread can only write
        // buffer `par^1` next iteration after passing THIS barrier, which
        // readers of `par` are still behind until they finish reading.

        // Redundant per-thread softmax (broadcast smem reads, K=5)
        float m[K];
        float mx = -INFINITY;
#pragma unroll
        for (int k = 0; k < K; k++) {
            const float dist = b[k] - 2.0f * (s_part[par][0][k] + s_part[par][1][k] +
                                              s_part[par][2][k] + s_part[par][3][k]);
            m[k] = dist;
            mx = fmaxf(mx, dist);
        }
        float sum = 0.f;
#pragma unroll
        for (int k = 0; k < K; k++) { m[k] = __expf(m[k] - mx); sum += m[k]; }
        const float inv = 1.0f / sum;
#pragma unroll
        for (int k = 0; k < K; k++) m[k] *= inv;

        if (t < K) out_map[(size_t)row * K + t] = m[t];
        if (t == K) {
            float pr = 0.f;
#pragma unroll
            for (int k = 0; k < K; k++) pr += m[k] * sw[k];
            out_pred[row] = pr;
        }

        // reconstructed row slice
        float4 r;
        r.x = m[0] * c4[0].x; r.y = m[0] * c4[0].y;
        r.z = m[0] * c4[0].z; r.w = m[0] * c4[0].w;
#pragma unroll
        for (int k = 1; k < K; k++) {
            r.x += m[k] * c4[k].x;
            r.y += m[k] * c4[k].y;
            r.z += m[k] * c4[k].z;
            r.w += m[k] * c4[k].w;
        }
        ((float4*)(out_rec + (size_t)row * D))[t] = r;

        par ^= 1;
        row = next;
        xv = xn;
    }
}

extern "C" void kernel_launch(void* const* d_in, const int* in_sizes, int n_in,
                              void* d_out, int out_size) {
    // metadata order: x, is_protected, alpha_p, classif_w, centroids
    const float* x     = (const float*)d_in[0];
    const float* alpha = (const float*)d_in[2];
    const float* cw    = (const float*)d_in[3];
    const float* cent  = (const float*)d_in[4];
    const int n = in_sizes[1];  // N

    float* out      = (float*)d_out;
    float* out_map  = out;                      // N*K
    float* out_rec  = out + (size_t)n * K;      // N*D
    float* out_pred = out_rec + (size_t)n * D;  // N

    lfr_blockrow_kernel<<<NBLOCKS, TPB>>>(x, alpha, cw, cent,
                                          out_map, out_rec, out_pred, n);
}

// round 10
// speedup vs baseline: 1.0883x; 1.0883x over previous
#include <cuda_runtime.h>
#include <cstdint>
#include <math.h>

#define D 512
#define K 5
#define WARPS 2
#define TPB (WARPS * 32)
#define NBLOCKS 4096     // 8192 warps -> 8 rows per warp
#define S 4              // cp.async ring depth per warp

__device__ __forceinline__ void cp_async16(uint32_t smem_addr, const void* gptr) {
    asm volatile("cp.async.cg.shared.global [%0], [%1], 16;\n"
                 :: "r"(smem_addr), "l"(gptr));
}
__device__ __forceinline__ void cp_commit() {
    asm volatile("cp.async.commit_group;\n");
}
template <int N>
__device__ __forceinline__ void cp_wait() {
    asm volatile("cp.async.wait_group %0;\n" :: "n"(N));
}

__global__ __launch_bounds__(TPB, 7) void lfr_ring_kernel(
    const float* __restrict__ x,
    const float* __restrict__ alpha,
    const float* __restrict__ classif_w,
    const float* __restrict__ centroids,
    float* __restrict__ out_map,   // (N, K)
    float* __restrict__ out_rec,   // (N, D)
    float* __restrict__ out_pred,  // (N,)
    int n)
{
    __shared__ float ring[WARPS][S][D];   // 16 KB

    const int lane   = threadIdx.x & 31;
    const int warp   = threadIdx.x >> 5;
    const int gwarp  = (blockIdx.x * TPB + threadIdx.x) >> 5;
    const int nwarps = (gridDim.x * TPB) >> 5;

    // Register caches: lane owns d = (i*32+lane)*4 .. +3, i in 0..3
    float4 a4[4];
    float4 c4[4][K];
#pragma unroll
    for (int i = 0; i < 4; i++) {
        const int d0 = (i * 32 + lane) * 4;
        a4[i] = *(const float4*)(alpha + d0);
#pragma unroll
        for (int k = 0; k < K; k++)
            c4[i][k] = *(const float4*)(centroids + k * D + d0);
    }

    // b[k] = sum_d alpha_d c_kd^2 ; sw[k] = sigmoid(classif_w[k])
    float b[K], sw[K];
#pragma unroll
    for (int k = 0; k < K; k++) {
        float s = 0.f;
#pragma unroll
        for (int i = 0; i < 4; i++) {
            s += a4[i].x * c4[i][k].x * c4[i][k].x
               + a4[i].y * c4[i][k].y * c4[i][k].y
               + a4[i].z * c4[i][k].z * c4[i][k].z
               + a4[i].w * c4[i][k].w * c4[i][k].w;
        }
#pragma unroll
        for (int o = 16; o; o >>= 1) s += __shfl_xor_sync(0xffffffffu, s, o);
        b[k] = s;
        sw[k] = 1.0f / (1.0f + __expf(-classif_w[k]));
    }

    const uint32_t rbase =
        (uint32_t)__cvta_generic_to_shared(&ring[warp][0][0]);

    // Prologue: queue S rows into the ring (empty commit groups keep count)
#pragma unroll
    for (int s = 0; s < S; s++) {
        const int r = gwarp + s * nwarps;
        if (r < n) {
            const float* xr = x + (size_t)r * D;
#pragma unroll
            for (int i = 0; i < 4; i++) {
                const int d0 = (i * 32 + lane) * 4;
                cp_async16(rbase + (uint32_t)(s * D + d0) * 4u, xr + d0);
            }
        }
        cp_commit();
    }

    int slot = 0;
    for (int row = gwarp; row < n; row += nwarps) {
        cp_wait<S - 1>();   // oldest group (current slot) complete

        // Read this row's x from the ring (each thread reads what it wrote)
        float4 xv[4];
#pragma unroll
        for (int i = 0; i < 4; i++)
            xv[i] = *(const float4*)&ring[warp][slot][(i * 32 + lane) * 4];

        // Refill this slot with row + S*stride (smem write lands ~600cyc
        // after the LDS above already executed — no hazard)
        {
            const int r = row + S * nwarps;
            if (r < n) {
                const float* xr = x + (size_t)r * D;
#pragma unroll
                for (int i = 0; i < 4; i++) {
                    const int d0 = (i * 32 + lane) * 4;
                    cp_async16(rbase + (uint32_t)(slot * D + d0) * 4u, xr + d0);
                }
            }
            cp_commit();
        }

        // dot_k = sum_d alpha_d x_d c_kd
        float dot[K];
#pragma unroll
        for (int k = 0; k < K; k++) dot[k] = 0.f;
#pragma unroll
        for (int i = 0; i < 4; i++) {
            const float tx = xv[i].x * a4[i].x;
            const float ty = xv[i].y * a4[i].y;
            const float tz = xv[i].z * a4[i].z;
            const float tw = xv[i].w * a4[i].w;
#pragma unroll
            for (int k = 0; k < K; k++) {
                dot[k] += tx * c4[i][k].x + ty * c4[i][k].y +
                          tz * c4[i][k].z + tw * c4[i][k].w;
            }
        }
#pragma unroll
        for (int k = 0; k < K; k++) {
            float s = dot[k];
#pragma unroll
            for (int o = 16; o; o >>= 1) s += __shfl_xor_sync(0xffffffffu, s, o);
            dot[k] = s;
        }

        // softmax over dist'[k] = b[k] - 2*dot[k]
        float m[K];
        float mx = -INFINITY;
#pragma unroll
        for (int k = 0; k < K; k++) {
            m[k] = b[k] - 2.0f * dot[k];
            mx = fmaxf(mx, m[k]);
        }
        float sum = 0.f;
#pragma unroll
        for (int k = 0; k < K; k++) { m[k] = __expf(m[k] - mx); sum += m[k]; }
        const float inv = 1.0f / sum;
#pragma unroll
        for (int k = 0; k < K; k++) m[k] *= inv;

        if (lane < K) out_map[(size_t)row * K + lane] = m[lane];
        if (lane == 0) {
            float p = 0.f;
#pragma unroll
            for (int k = 0; k < K; k++) p += m[k] * sw[k];
            out_pred[row] = p;
        }

        // reconstructed = mapping @ centroids (register-resident)
        float4* rr = (float4*)(out_rec + (size_t)row * D);
#pragma unroll
        for (int i = 0; i < 4; i++) {
            float4 r;
            r.x = m[0] * c4[i][0].x; r.y = m[0] * c4[i][0].y;
            r.z = m[0] * c4[i][0].z; r.w = m[0] * c4[i][0].w;
#pragma unroll
            for (int k = 1; k < K; k++) {
                r.x += m[k] * c4[i][k].x;
                r.y += m[k] * c4[i][k].y;
                r.z += m[k] * c4[i][k].z;
                r.w += m[k] * c4[i][k].w;
            }
            rr[i * 32 + lane] = r;
        }

        slot = (slot + 1) & (S - 1);
    }
}

extern "C" void kernel_launch(void* const* d_in, const int* in_sizes, int n_in,
                              void* d_out, int out_size) {
    // metadata order: x, is_protected, alpha_p, classif_w, centroids
    const float* x     = (const float*)d_in[0];
    const float* alpha = (const float*)d_in[2];
    const float* cw    = (const float*)d_in[3];
    const float* cent  = (const float*)d_in[4];
    const int n = in_sizes[1];  // N

    float* out      = (float*)d_out;
    float* out_map  = out;                      // N*K
    float* out_rec  = out + (size_t)n * K;      // N*D
    float* out_pred = out_rec + (size_t)n * D;  // N

    lfr_ring_kernel<<<NBLOCKS, TPB>>>(x, alpha, cw, cent,
                                      out_map, out_rec, out_pred, n);
}